// round 14
// baseline (speedup 1.0000x reference)
#include <cuda_runtime.h>
#include <cuda_bf16.h>
#include <math.h>

// ---------------- problem constants ----------------
#define BB 2
#define NN 2048
#define DD 128
#define HH 8
#define DH 16
#define LL 3
#define ROWS (BB*NN)        // 4096
#define SCALE 0.25f         // 1/sqrt(16)
#define LOG2E 1.4426950408889634f
#define NEGL  (-1.5e9f)     // masked logit, log2 domain
#define EPS   1e-5f
#define KS    8             // key-split chunks
#define CHUNK (NN/KS)       // 256 keys per chunk

// weight presplit offsets (uint elements, linear layout)
#define OFF_IN   0
#define SZ_IN    (DD*DD)
#define OFF_QKV  (OFF_IN + SZ_IN)
#define SZ_QKV   (LL*3*DD*DD)
#define OFF_OUT  (OFF_QKV + SZ_QKV)
#define SZ_OUT   (LL*DD*DD)
#define OFF_FF1  (OFF_OUT + SZ_OUT)
#define SZ_FF1   (LL*4*DD*DD)
#define OFF_FF2  (OFF_FF1 + SZ_FF1)
#define SZ_FF2   (LL*DD*4*DD)
#define W_TOTAL  (OFF_FF2 + SZ_FF2)

__device__ __forceinline__ float ex2(float x) {
    float r; asm("ex2.approx.ftz.f32 %0,%1;" : "=f"(r) : "f"(x)); return r;
}
__device__ __forceinline__ unsigned tf32c(float x) {
    unsigned r; asm("cvt.rna.tf32.f32 %0,%1;" : "=r"(r) : "f"(x)); return r;
}
__device__ __forceinline__ void mma8(float c[4], unsigned a0, unsigned a1,
                                     unsigned a2, unsigned a3,
                                     unsigned b0, unsigned b1) {
    asm volatile(
        "mma.sync.aligned.m16n8k8.row.col.f32.tf32.tf32.f32 "
        "{%0,%1,%2,%3},{%4,%5,%6,%7},{%8,%9},{%0,%1,%2,%3};"
        : "+f"(c[0]), "+f"(c[1]), "+f"(c[2]), "+f"(c[3])
        : "r"(a0), "r"(a1), "r"(a2), "r"(a3), "r"(b0), "r"(b1));
}
__device__ __forceinline__ void tsplit(float x, unsigned& hi, unsigned& lo) {
    hi = tf32c(x);
    lo = tf32c(x - __uint_as_float(hi));
}

// ---------------- scratch (device globals; no allocation allowed) ----------
__device__ float g_h  [ROWS*DD];
__device__ float g_x  [ROWS*DD];
__device__ float g_qkv[ROWS*3*DD];
__device__ float g_o  [ROWS*DD];
__device__ float g_f  [ROWS*4*DD];
__device__ float g_part[4*ROWS*DD];     // split-K GEMM partials
__device__ float g_pacc[ROWS*HH*KS*16];
__device__ float g_pml [ROWS*HH*KS*2];
__device__ float g_mean[ROWS];
__device__ float g_rstd[ROWS];
__device__ unsigned g_whi[W_TOTAL];
__device__ unsigned g_wlo[W_TOTAL];
__device__ int   g_isatom[ROWS];
__device__ int   g_mask  [ROWS];

// ---------------- merged weight presplit (linear layout) ----------------
__global__ void presplit_all_kernel(const float* __restrict__ w0, const float* __restrict__ w1,
                                    const float* __restrict__ w2, const float* __restrict__ w3,
                                    const float* __restrict__ w4,
                                    unsigned* __restrict__ hi, unsigned* __restrict__ lo) {
    int gi = blockIdx.x*blockDim.x + threadIdx.x;
    if (gi >= W_TOTAL) return;
    float v;
    if      (gi < OFF_QKV) v = w0[gi - OFF_IN];
    else if (gi < OFF_OUT) v = w1[gi - OFF_QKV];
    else if (gi < OFF_FF1) v = w2[gi - OFF_OUT];
    else if (gi < OFF_FF2) v = w3[gi - OFF_FF1];
    else                   v = w4[gi - OFF_FF2];
    unsigned h, l;
    tsplit(v, h, l);
    hi[gi] = h; lo[gi] = l;
}

// ---------------- bool normalization (format-agnostic) ----------------
__global__ void norm_bool_kernel(const unsigned char* __restrict__ raw, int count,
                                 int* __restrict__ out) {
    __shared__ int s_other;
    if (threadIdx.x == 0) s_other = 0;
    __syncthreads();
    const unsigned int* w = (const unsigned int*)raw;
    int nw = count / 4;
    int other = 0;
    for (int i = threadIdx.x; i < nw; i += blockDim.x) {
        unsigned int v = w[i];
        if (v != 0u && v != 1u && v != 0x3f800000u) other = 1;
    }
    if (other) atomicOr(&s_other, 1);
    __syncthreads();
    bool byteFmt = (s_other != 0);
    for (int i = threadIdx.x; i < count; i += blockDim.x) {
        out[i] = byteFmt ? (raw[i] != 0) : (w[i] != 0u);
    }
}

// ---------------- embedding gather ----------------
__global__ void embed_kernel(const float* __restrict__ atom_embed,
                             const float* __restrict__ cons_embed,
                             const int* __restrict__ atom_id,
                             const int* __restrict__ isatom,
                             float* __restrict__ e) {
    int row = blockIdx.x, t = threadIdx.x;
    int id = atom_id[row];
    id = id < 0 ? 0 : (id > 31 ? 31 : id);
    float v = isatom[row] ? atom_embed[id*DD + t] : cons_embed[t];
    e[row*DD + t] = v;
}

// ---------------- block reduction helper (128 threads) ----------------
__device__ __forceinline__ float blockReduceSum128(float v, float* sred) {
    #pragma unroll
    for (int o = 16; o; o >>= 1) v += __shfl_xor_sync(0xffffffffu, v, o);
    int wid = threadIdx.x >> 5;
    if ((threadIdx.x & 31) == 0) sred[wid] = v;
    __syncthreads();
    float r = sred[0] + sred[1] + sred[2] + sred[3];
    __syncthreads();
    return r;
}

// ---------------- LN stats: warp per row (shuffles only) ----------------
__global__ void stats_kernel(const float* __restrict__ in,
                             float* __restrict__ mean, float* __restrict__ rstd) {
    int gw = (blockIdx.x*blockDim.x + threadIdx.x) >> 5;
    int lane = threadIdx.x & 31;
    float4 v = *(const float4*)(in + (size_t)gw*DD + lane*4);
    float s  = v.x + v.y + v.z + v.w;
    float s2 = v.x*v.x + v.y*v.y + v.z*v.z + v.w*v.w;
    #pragma unroll
    for (int o = 16; o; o >>= 1) {
        s  += __shfl_xor_sync(0xffffffffu, s,  o);
        s2 += __shfl_xor_sync(0xffffffffu, s2, o);
    }
    if (lane == 0) {
        float mu = s * (1.0f/DD);
        mean[gw] = mu;
        rstd[gw] = rsqrtf(s2 * (1.0f/DD) - mu*mu + EPS);
    }
}

// ---------------- MMA GEMM (attention-style fragments, no smem/syncs) ------
// C[M,Nc] = A'[M,K] @ W[Nc,K]^T (+bias/epilogue).  W pre-split (hi/lo tf32).
// Block = 8 warps (4m x 2n) = 128x64 tile; warp = m32 x n32.
// PARTS==1: full K, epilogue fused (MODE 0 bias, 2 bias+GELU).
// PARTS>1:  K split over gridDim.z; raw partials to Cpart (combine applies
//           bias/res epilogue).
template<int MODE, bool LNA, int PARTS>
__global__ __launch_bounds__(256)
void gemm_mma(const float* __restrict__ A,
              const unsigned* __restrict__ Whi, const unsigned* __restrict__ Wlo,
              const float* __restrict__ bias, float* __restrict__ C,
              int M, int Nc, int K,
              const float* __restrict__ meanp, const float* __restrict__ rstdp,
              const float* __restrict__ lng, const float* __restrict__ lnb) {
    const int tid = threadIdx.x;
    const int w = tid >> 5, lane = tid & 31;
    const int g = lane >> 2, t4 = lane & 3;
    const int wm = w >> 1, wn = w & 1;
    const int m0 = blockIdx.y * 128, n0 = blockIdx.x * 64;
    const int kpart = K / PARTS;
    const int kb0 = blockIdx.z * kpart;

    float mu[2][2], rs[2][2];
    if (LNA) {
        #pragma unroll
        for (int mt = 0; mt < 2; mt++)
            #pragma unroll
            for (int hf = 0; hf < 2; hf++) {
                int row = m0 + wm*32 + mt*16 + g + hf*8;
                mu[mt][hf] = meanp[row];
                rs[mt][hf] = rstdp[row];
            }
    }

    float c[2][4][4] = {};

    for (int kb = kb0; kb < kb0 + kpart; kb += 8) {
        float lg0, lg4, lb0, lb4;
        if (LNA) {
            lg0 = lng[kb+t4]; lg4 = lng[kb+t4+4];
            lb0 = lnb[kb+t4]; lb4 = lnb[kb+t4+4];
        }
        unsigned ah[2][4], al[2][4];
        #pragma unroll
        for (int mt = 0; mt < 2; mt++) {
            const float* r0 = A + (size_t)(m0 + wm*32 + mt*16 + g)*K + kb;
            const float* r8 = r0 + 8*K;
            float a0 = r0[t4], a1 = r8[t4], a2 = r0[t4+4], a3 = r8[t4+4];
            if (LNA) {
                a0 = (a0 - mu[mt][0])*rs[mt][0]*lg0 + lb0;
                a1 = (a1 - mu[mt][1])*rs[mt][1]*lg0 + lb0;
                a2 = (a2 - mu[mt][0])*rs[mt][0]*lg4 + lb4;
                a3 = (a3 - mu[mt][1])*rs[mt][1]*lg4 + lb4;
            }
            tsplit(a0, ah[mt][0], al[mt][0]);
            tsplit(a1, ah[mt][1], al[mt][1]);
            tsplit(a2, ah[mt][2], al[mt][2]);
            tsplit(a3, ah[mt][3], al[mt][3]);
        }
        #pragma unroll
        for (int nt = 0; nt < 4; nt++) {
            size_t nr = (size_t)(n0 + wn*32 + nt*8 + g)*K + kb;
            unsigned bh0 = Whi[nr+t4], bh1 = Whi[nr+t4+4];
            unsigned bl0 = Wlo[nr+t4], bl1 = Wlo[nr+t4+4];
            #pragma unroll
            for (int mt = 0; mt < 2; mt++) {
                mma8(c[mt][nt], ah[mt][0], ah[mt][1], ah[mt][2], ah[mt][3], bh0, bh1);
                mma8(c[mt][nt], al[mt][0], al[mt][1], al[mt][2], al[mt][3], bh0, bh1);
                mma8(c[mt][nt], ah[mt][0], ah[mt][1], ah[mt][2], ah[mt][3], bl0, bl1);
            }
        }
    }

    if (PARTS == 1) {
        #pragma unroll
        for (int mt = 0; mt < 2; mt++)
            #pragma unroll
            for (int nt = 0; nt < 4; nt++) {
                int col = n0 + wn*32 + nt*8 + t4*2;
                float2 b2 = *(const float2*)(bias + col);
                #pragma unroll
                for (int hf = 0; hf < 2; hf++) {
                    int row = m0 + wm*32 + mt*16 + g + hf*8;
                    float vx = c[mt][nt][hf*2]   + b2.x;
                    float vy = c[mt][nt][hf*2+1] + b2.y;
                    if (MODE == 2) {
                        vx = 0.5f*vx*(1.0f + erff(vx*0.70710678118654752f));
                        vy = 0.5f*vy*(1.0f + erff(vy*0.70710678118654752f));
                    }
                    *(float2*)(C + (size_t)row*Nc + col) = make_float2(vx, vy);
                }
            }
    } else {
        float* dst = C + (size_t)blockIdx.z*M*Nc;
        #pragma unroll
        for (int mt = 0; mt < 2; mt++)
            #pragma unroll
            for (int nt = 0; nt < 4; nt++) {
                int col = n0 + wn*32 + nt*8 + t4*2;
                #pragma unroll
                for (int hf = 0; hf < 2; hf++) {
                    int row = m0 + wm*32 + mt*16 + g + hf*8;
                    *(float2*)(dst + (size_t)row*Nc + col) =
                        make_float2(c[mt][nt][hf*2], c[mt][nt][hf*2+1]);
                }
            }
    }
}

// ---------------- split-K combine: sum 4 partials + bias (+res) ------------
// MODE 0: +bias | MODE 1: +bias +res (res may alias C)
template<int MODE>
__global__ void combine_kernel(const float* __restrict__ part,
                               const float* __restrict__ bias,
                               const float* __restrict__ res,
                               float* __restrict__ C, int total, int Nc) {
    int i = (blockIdx.x*blockDim.x + threadIdx.x)*4;
    if (i >= total) return;
    float4 v0 = *(const float4*)(part + i);
    float4 v1 = *(const float4*)(part + (size_t)total + i);
    float4 v2 = *(const float4*)(part + 2*(size_t)total + i);
    float4 v3 = *(const float4*)(part + 3*(size_t)total + i);
    float4 b = *(const float4*)(bias + (i % Nc));
    float4 o;
    o.x = v0.x+v1.x+v2.x+v3.x + b.x;
    o.y = v0.y+v1.y+v2.y+v3.y + b.y;
    o.z = v0.z+v1.z+v2.z+v3.z + b.z;
    o.w = v0.w+v1.w+v2.w+v3.w + b.w;
    if (MODE == 1) {
        float4 r = *(const float4*)(res + i);
        o.x += r.x; o.y += r.y; o.z += r.z; o.w += r.w;
    }
    *(float4*)(C + i) = o;
}

// ---------------- full tensor-core flash attention (split-K partials) ------
// (R12 verified — unchanged)
__global__ __launch_bounds__(256)
void attn_tc_kernel(const float* __restrict__ qkv, const float* __restrict__ adj,
                    const int* __restrict__ mask, const float* __restrict__ sbp,
                    float* __restrict__ pacc, float* __restrict__ pml) {
    const int b = blockIdx.y >> 3, ck = blockIdx.y & 7;
    const int n0 = blockIdx.x * 32;
    const int tid = threadIdx.x;
    const int hh = tid >> 5, lane = tid & 31;
    const int g = lane >> 2, t4 = lane & 3;
    const float sbl = (*sbp) * LOG2E;
    const float SC2 = SCALE * LOG2E;
    const float* adjb = adj + (size_t)b*NN*NN;
    const int* maskb = mask + b*NN;
    const float* qkvb = qkv + (size_t)b*NN*384;

    unsigned qh[2][2][4], ql[2][2][4];
    #pragma unroll
    for (int mt = 0; mt < 2; mt++)
        #pragma unroll
        for (int ks = 0; ks < 2; ks++) {
            const float* r0 = qkvb + (size_t)(n0 + mt*16 + g)*384 + hh*16 + ks*8;
            const float* r8 = r0 + 8*384;
            tsplit(r0[t4],   qh[mt][ks][0], ql[mt][ks][0]);
            tsplit(r8[t4],   qh[mt][ks][1], ql[mt][ks][1]);
            tsplit(r0[t4+4], qh[mt][ks][2], ql[mt][ks][2]);
            tsplit(r8[t4+4], qh[mt][ks][3], ql[mt][ks][3]);
        }
    int mqr[2][2];
    #pragma unroll
    for (int mt = 0; mt < 2; mt++)
        #pragma unroll
        for (int hf = 0; hf < 2; hf++)
            mqr[mt][hf] = maskb[n0 + mt*16 + g + hf*8];

    float mrun[2][2], lrun[2][2];
    #pragma unroll
    for (int mt = 0; mt < 2; mt++)
        #pragma unroll
        for (int hf = 0; hf < 2; hf++) { mrun[mt][hf] = -INFINITY; lrun[mt][hf] = 0.0f; }
    float co[2][2][4] = {};

    const int kBeg = ck*CHUNK, kEnd = ck*CHUNK + CHUNK;
    for (int k0 = kBeg; k0 < kEnd; k0 += 32) {
        float s[2][4][4] = {};
        #pragma unroll
        for (int nt = 0; nt < 4; nt++)
            #pragma unroll
            for (int ks = 0; ks < 2; ks++) {
                const float* kr = qkvb + (size_t)(k0 + nt*8 + g)*384 + 128 + hh*16 + ks*8;
                unsigned bh0, bl0, bh1, bl1;
                tsplit(kr[t4],   bh0, bl0);
                tsplit(kr[t4+4], bh1, bl1);
                #pragma unroll
                for (int mt = 0; mt < 2; mt++) {
                    mma8(s[mt][nt], qh[mt][ks][0], qh[mt][ks][1], qh[mt][ks][2], qh[mt][ks][3], bh0, bh1);
                    mma8(s[mt][nt], ql[mt][ks][0], ql[mt][ks][1], ql[mt][ks][2], ql[mt][ks][3], bh0, bh1);
                    mma8(s[mt][nt], qh[mt][ks][0], qh[mt][ks][1], qh[mt][ks][2], qh[mt][ks][3], bl0, bl1);
                }
            }
        #pragma unroll
        for (int nt = 0; nt < 4; nt++) {
            int gk = k0 + nt*8 + t4*2;
            int mk0 = maskb[gk], mk1 = maskb[gk+1];
            #pragma unroll
            for (int mt = 0; mt < 2; mt++)
                #pragma unroll
                for (int hf = 0; hf < 2; hf++) {
                    int gq = n0 + mt*16 + g + hf*8;
                    float2 a2 = *(const float2*)(adjb + (size_t)gq*NN + gk);
                    bool ok0 = mqr[mt][hf] ? (mk0 != 0) : (gq == gk);
                    bool ok1 = mqr[mt][hf] ? (mk1 != 0) : (gq == gk+1);
                    s[mt][nt][hf*2]   = fmaf(s[mt][nt][hf*2],   SC2, fmaf(a2.x, sbl, ok0 ? 0.0f : NEGL));
                    s[mt][nt][hf*2+1] = fmaf(s[mt][nt][hf*2+1], SC2, fmaf(a2.y, sbl, ok1 ? 0.0f : NEGL));
                }
        }
        #pragma unroll
        for (int mt = 0; mt < 2; mt++)
            #pragma unroll
            for (int hf = 0; hf < 2; hf++) {
                float mloc = s[mt][0][hf*2];
                mloc = fmaxf(mloc, s[mt][0][hf*2+1]);
                #pragma unroll
                for (int nt = 1; nt < 4; nt++) {
                    mloc = fmaxf(mloc, s[mt][nt][hf*2]);
                    mloc = fmaxf(mloc, s[mt][nt][hf*2+1]);
                }
                mloc = fmaxf(mloc, __shfl_xor_sync(0xffffffffu, mloc, 1));
                mloc = fmaxf(mloc, __shfl_xor_sync(0xffffffffu, mloc, 2));
                float mn = fmaxf(mrun[mt][hf], mloc);
                float corr = ex2(mrun[mt][hf] - mn);
                mrun[mt][hf] = mn;
                #pragma unroll
                for (int nt2 = 0; nt2 < 2; nt2++) {
                    co[mt][nt2][hf*2]   *= corr;
                    co[mt][nt2][hf*2+1] *= corr;
                }
                float ls = 0.0f;
                #pragma unroll
                for (int nt = 0; nt < 4; nt++) {
                    float p0 = ex2(s[mt][nt][hf*2]   - mn);
                    float p1 = ex2(s[mt][nt][hf*2+1] - mn);
                    s[mt][nt][hf*2] = p0; s[mt][nt][hf*2+1] = p1;
                    ls += p0 + p1;
                }
                ls += __shfl_xor_sync(0xffffffffu, ls, 1);
                ls += __shfl_xor_sync(0xffffffffu, ls, 2);
                lrun[mt][hf] = lrun[mt][hf]*corr + ls;
            }
        #pragma unroll
        for (int ntk = 0; ntk < 4; ntk++) {
            unsigned ah[2][4], al[2][4];
            #pragma unroll
            for (int mt = 0; mt < 2; mt++) {
                tsplit(s[mt][ntk][0], ah[mt][0], al[mt][0]);
                tsplit(s[mt][ntk][2], ah[mt][1], al[mt][1]);
                tsplit(s[mt][ntk][1], ah[mt][2], al[mt][2]);
                tsplit(s[mt][ntk][3], ah[mt][3], al[mt][3]);
            }
            #pragma unroll
            for (int nt2 = 0; nt2 < 2; nt2++) {
                const float* vr = qkvb + (size_t)(k0 + ntk*8 + 2*t4)*384 + 256 + hh*16 + nt2*8 + g;
                unsigned vh0, vl0, vh1, vl1;
                tsplit(vr[0],   vh0, vl0);
                tsplit(vr[384], vh1, vl1);
                #pragma unroll
                for (int mt = 0; mt < 2; mt++) {
                    mma8(co[mt][nt2], ah[mt][0], ah[mt][1], ah[mt][2], ah[mt][3], vh0, vh1);
                    mma8(co[mt][nt2], al[mt][0], al[mt][1], al[mt][2], al[mt][3], vh0, vh1);
                    mma8(co[mt][nt2], ah[mt][0], ah[mt][1], ah[mt][2], ah[mt][3], vl0, vl1);
                }
            }
        }
    }
    #pragma unroll
    for (int mt = 0; mt < 2; mt++)
        #pragma unroll
        for (int hf = 0; hf < 2; hf++) {
            int q = n0 + mt*16 + g + hf*8;
            size_t p = (((size_t)(b*NN + q))*HH + hh)*KS + ck;
            if (t4 == 0) {
                pml[p*2]   = mrun[mt][hf];
                pml[p*2+1] = lrun[mt][hf];
            }
            #pragma unroll
            for (int nt2 = 0; nt2 < 2; nt2++)
                *(float2*)(pacc + p*16 + nt2*8 + t4*2) =
                    make_float2(co[mt][nt2][hf*2], co[mt][nt2][hf*2+1]);
        }
}

// ---------------- split-K reduce (base-2 weights) ----------------
__global__ void attn_reduce_kernel(const float* __restrict__ pacc,
                                   const float* __restrict__ pml,
                                   float* __restrict__ o) {
    int t = blockIdx.x * blockDim.x + threadIdx.x;
    if (t >= ROWS*HH) return;
    size_t base = (size_t)t * KS;
    float mv[KS], lv[KS];
    float M = -INFINITY;
    #pragma unroll
    for (int c = 0; c < KS; c++) {
        mv[c] = pml[(base+c)*2];
        lv[c] = pml[(base+c)*2+1];
        M = fmaxf(M, mv[c]);
    }
    float w[KS]; float L = 0.0f;
    #pragma unroll
    for (int c = 0; c < KS; c++) { w[c] = ex2(mv[c] - M); L += w[c]*lv[c]; }
    float inv = 1.0f / L;
    int qrow = t >> 3, hh = t & 7;
    float* op = o + (size_t)qrow*DD + hh*DH;
    #pragma unroll
    for (int d = 0; d < 16; d++) {
        float s = 0.0f;
        #pragma unroll
        for (int c = 0; c < KS; c++) s += w[c] * pacc[(base+c)*16 + d];
        op[d] = s * inv;
    }
}

// ---------------- head: gather root, LN, dot ----------------
__global__ void head_kernel(const float* __restrict__ h, const float* __restrict__ g,
                            const float* __restrict__ bb, const float* __restrict__ w,
                            const float* __restrict__ hb, const int* __restrict__ root,
                            float* __restrict__ out) {
    __shared__ float sred[4];
    int t = threadIdx.x;
    for (int b = 0; b < BB; b++) {
        int row = root[b];
        float v = h[((size_t)b*NN + row)*DD + t];
        float mean = blockReduceSum128(v, sred) * (1.0f/DD);
        float d = v - mean;
        float var = blockReduceSum128(d*d, sred) * (1.0f/DD);
        float p = d * rsqrtf(var + EPS) * g[t] + bb[t];
        float s = blockReduceSum128(p * w[t], sred);
        if (t == 0) out[b] = s + hb[0];
    }
}

// ---------------- launch ----------------
extern "C" void kernel_launch(void* const* d_in, const int* in_sizes, int n_in,
                              void* d_out, int out_size) {
    const float* atom_embed = (const float*)d_in[0];
    const float* cons_embed = (const float*)d_in[1];
    const float* in_w   = (const float*)d_in[2];
    const float* in_b   = (const float*)d_in[3];
    const float* qkv_w  = (const float*)d_in[4];
    const float* qkv_b  = (const float*)d_in[5];
    const float* out_w  = (const float*)d_in[6];
    const float* out_b  = (const float*)d_in[7];
    const float* ln1_g  = (const float*)d_in[8];
    const float* ln1_b  = (const float*)d_in[9];
    const float* ln2_g  = (const float*)d_in[10];
    const float* ln2_b  = (const float*)d_in[11];
    const float* ff1_w  = (const float*)d_in[12];
    const float* ff1_b  = (const float*)d_in[13];
    const float* ff2_w  = (const float*)d_in[14];
    const float* ff2_b  = (const float*)d_in[15];
    const float* struct_bias = (const float*)d_in[16];
    const float* head_ln_g = (const float*)d_in[17];
    const float* head_ln_b = (const float*)d_in[18];
    const float* head_w = (const float*)d_in[19];
    const float* head_b = (const float*)d_in[20];
    const float* adjacency = (const float*)d_in[21];
    const unsigned char* is_atom_raw = (const unsigned char*)d_in[22];
    const int* atom_id  = (const int*)d_in[23];
    const unsigned char* mask_raw = (const unsigned char*)d_in[24];
    const int* root_idx = (const int*)d_in[25];
    float* outp = (float*)d_out;

    float *h, *x, *qkv, *o, *f, *part, *pacc, *pml, *mean, *rstd;
    unsigned *whi, *wlo;
    int *im, *mk;
    cudaGetSymbolAddress((void**)&h,  g_h);
    cudaGetSymbolAddress((void**)&x,  g_x);
    cudaGetSymbolAddress((void**)&qkv, g_qkv);
    cudaGetSymbolAddress((void**)&o,  g_o);
    cudaGetSymbolAddress((void**)&f,  g_f);
    cudaGetSymbolAddress((void**)&part, g_part);
    cudaGetSymbolAddress((void**)&pacc, g_pacc);
    cudaGetSymbolAddress((void**)&pml,  g_pml);
    cudaGetSymbolAddress((void**)&mean, g_mean);
    cudaGetSymbolAddress((void**)&rstd, g_rstd);
    cudaGetSymbolAddress((void**)&whi, g_whi);
    cudaGetSymbolAddress((void**)&wlo, g_wlo);
    cudaGetSymbolAddress((void**)&im, g_isatom);
    cudaGetSymbolAddress((void**)&mk, g_mask);

    presplit_all_kernel<<<(W_TOTAL+255)/256, 256>>>(in_w, qkv_w, out_w, ff1_w, ff2_w, whi, wlo);

    norm_bool_kernel<<<1, 256>>>(is_atom_raw, ROWS, im);
    norm_bool_kernel<<<1, 256>>>(mask_raw,    ROWS, mk);
    embed_kernel<<<ROWS, 128>>>(atom_embed, cons_embed, atom_id, im, x);

    const int TOT = ROWS*DD;
    // in-proj: thin, split-K4 (K=128), MODE0 combine
    gemm_mma<0,false,4><<<dim3(2,32,4), 256>>>(x, whi+OFF_IN, wlo+OFF_IN, in_b, part,
                                               ROWS, DD, DD, nullptr, nullptr, nullptr, nullptr);
    combine_kernel<0><<<TOT/1024, 256>>>(part, in_b, nullptr, h, TOT, DD);

    for (int l = 0; l < LL; l++) {
        stats_kernel<<<ROWS/8, 256>>>(h, mean, rstd);
        // qkv: fat, LN fused, bias epilogue
        gemm_mma<0,true,1><<<dim3(6,32), 256>>>(h, whi+OFF_QKV + l*3*DD*DD, wlo+OFF_QKV + l*3*DD*DD,
                                                qkv_b + l*3*DD, qkv,
                                                ROWS, 3*DD, DD,
                                                mean, rstd, ln1_g + l*DD, ln1_b + l*DD);
        attn_tc_kernel<<<dim3(NN/32, KS*BB), 256>>>(qkv, adjacency, mk,
                                                    struct_bias + l, pacc, pml);
        attn_reduce_kernel<<<ROWS*HH/256, 256>>>(pacc, pml, o);
        // out-proj: thin, split-K4 (K=128), combine with residual
        gemm_mma<0,false,4><<<dim3(2,32,4), 256>>>(o, whi+OFF_OUT + l*DD*DD, wlo+OFF_OUT + l*DD*DD,
                                                   out_b + l*DD, part,
                                                   ROWS, DD, DD, nullptr, nullptr, nullptr, nullptr);
        combine_kernel<1><<<TOT/1024, 256>>>(part, out_b + l*DD, h, h, TOT, DD);
        stats_kernel<<<ROWS/8, 256>>>(h, mean, rstd);
        // ff1: fat, LN fused, bias+GELU epilogue
        gemm_mma<2,true,1><<<dim3(8,32), 256>>>(h, whi+OFF_FF1 + l*4*DD*DD, wlo+OFF_FF1 + l*4*DD*DD,
                                                ff1_b + l*4*DD, f,
                                                ROWS, 4*DD, DD,
                                                mean, rstd, ln2_g + l*DD, ln2_b + l*DD);
        // ff2: thin, split-K4 (K=512), combine with residual
        gemm_mma<0,false,4><<<dim3(2,32,4), 256>>>(f, whi+OFF_FF2 + l*DD*4*DD, wlo+OFF_FF2 + l*DD*4*DD,
                                                   ff2_b + l*DD, part,
                                                   ROWS, DD, 4*DD, nullptr, nullptr, nullptr, nullptr);
        combine_kernel<1><<<TOT/1024, 256>>>(part, ff2_b + l*DD, h, h, TOT, DD);
    }

    head_kernel<<<1, 128>>>(h, head_ln_g, head_ln_b, head_w, head_b, root_idx, outp);
}